// round 13
// baseline (speedup 1.0000x reference)
#include <cuda_runtime.h>
#include <cuda_fp16.h>
#include <cstdint>

// FDN reverb, fused persistent kernel. fp32 deinterleaved x-window (even
// logical vec4s in phys [0,1024), odd in [1024,2048)) + adjacent-pair outputs:
// every tap = 2-3 conflict-free LDS.128 shared by both outputs, misalignment
// resolved by compile-time register selection. Zero cvt / shfl in phase 1.
// y stashed fp16 (uint4/thread/tile). grid=296, 2 CTAs/SM, epoch barrier.

#define T_LEN    8388608
#define NCTA     296
#define TPB      512
#define TILE_V4  1024                  // vec4 per tile
#define NT7      272                   // 272 CTAs * 7 tiles + 24 * 6 = 2048
#define STASH_T  7
#define SMEM_BYTES (2048 * 16 + STASH_T * 512 * 16)   // 32 KB win + 56 KB stash

__device__ unsigned g_maxbits;  // monotone: deterministic across replays
__device__ unsigned g_bar;      // epoch barrier counter

__device__ __forceinline__ unsigned pk2(float a, float b) {
    __half2 h = __floats2half2_rn(a, b);
    return reinterpret_cast<unsigned&>(h);
}
__device__ __forceinline__ float2 upk2(unsigned u) {
    __half2 h = reinterpret_cast<__half2&>(u);
    return __half22float2(h);
}

__device__ __forceinline__ void acc4(float4& acc, float c, float4 v) {
    acc.x = fmaf(c, v.x, acc.x);
    acc.y = fmaf(c, v.y, acc.y);
    acc.z = fmaf(c, v.z, acc.z);
    acc.w = fmaf(c, v.w, acc.w);
}

// Tap for output pair at even absolute vec V (hv = V>>1), d = 4Q+R.
// a = V-Q; parity(a) = parity(Q) (compile-time). Deinterleave:
//   even vec e -> phys (e>>1)&1023 ; odd vec o -> ((o>>1)&1023) + 1024
template <int Q, int R>
__device__ __forceinline__ void tap2(const float4* __restrict__ sw, int hv,
                                     float c, float4& o0, float4& o1) {
    constexpr int  HQ = (Q + 1) / 2;     // hv - HQ == (V-Q)>>1
    constexpr bool AE = (Q & 1) == 0;    // a even?
    const int la = (hv - HQ) & 1023;

    float4 A = AE ? sw[la] : sw[la + 1024];
    float4 B = AE ? sw[la + 1024] : sw[(la + 1) & 1023];
    float4 t0, t1;
    if (R == 0) {
        t0 = A; t1 = B;
    } else {
        float4 P = AE ? sw[((la - 1) & 1023) + 1024] : sw[la];
        if (R == 1) {
            t0 = make_float4(P.w, A.x, A.y, A.z);
            t1 = make_float4(A.w, B.x, B.y, B.z);
        } else { // R == 2
            t0 = make_float4(P.z, P.w, A.x, A.y);
            t1 = make_float4(A.z, A.w, B.x, B.y);
        }
    }
    acc4(o0, c, t0);
    acc4(o1, c, t1);
}

__global__ void __launch_bounds__(TPB, 2)
fdn_fused(const float* __restrict__ x, const float* __restrict__ gain,
          const float* __restrict__ qmat, float* __restrict__ out) {
    extern __shared__ float4 sw[];           // deinterleaved window (2048)
    uint4* s_h4 = (uint4*)(sw + 2048);       // fp16 y stash (7*512 uint4)
    __shared__ float s_cm[8];
    __shared__ float s_red[TPB / 32];
    __shared__ float s_inv;

    const int t    = threadIdx.x;
    const int lane = t & 31;
    const int w    = t >> 5;
    const int b    = blockIdx.x;
    const int nt    = (b < NT7) ? 7 : 6;
    const int tile0 = (b < NT7) ? b * 7 : 6 * b + NT7;
    const int gv0   = tile0 * TILE_V4;
    const float4* xv = (const float4*)x;
    float4* ov = (float4*)out;

    // coefficients
    if (t < 8) {
        float s = 0.f;
#pragma unroll
        for (int j = 0; j < 8; j++) s += __ldg(qmat + j * 8 + t);
        s_cm[t] = 0.5f * s * __ldg(gain + t);
    }

    // preload halo tile (tile0-1) into its deinterleaved slot (zero below 0)
    {
        const int ssh = ((tile0 - 1) & 1) * 512;
        const int g0 = gv0 - TILE_V4 + 2 * t;
        const float4 z4 = make_float4(0.f, 0.f, 0.f, 0.f);
        sw[ssh + t]        = (g0 >= 0)     ? __ldg(xv + g0)     : z4;  // even vec
        sw[1024 + ssh + t] = (g0 + 1 >= 0) ? __ldg(xv + g0 + 1) : z4;  // odd vec
    }
    float4 r0 = __ldg(xv + gv0 + 2 * t);
    float4 r1 = __ldg(xv + gv0 + 2 * t + 1);
    __syncthreads();

    float cm[8];
#pragma unroll
    for (int n = 0; n < 8; n++) cm[n] = s_cm[n];

    // ---- phase 1: FIR; y -> fp16 SMEM stash; running max ----
    float m = 0.f;
#pragma unroll 1
    for (int s = 0; s < nt; s++) {
        const int ss = ((tile0 + s) & 1) * 512;
        sw[ss + t]        = r0;   // even vec V = gv0 + s*1024 + 2t
        sw[1024 + ss + t] = r1;   // odd vec V+1
        float4 c0 = r0, c1 = r1;
        __syncthreads();          // staging visible
        if (s + 1 < nt) {         // prefetch next tile under compute
            const int nb = gv0 + (s + 1) * TILE_V4 + 2 * t;
            r0 = __ldg(xv + nb);
            r1 = __ldg(xv + nb + 1);
        }
        const int hv = (tile0 + s) * 512 + t;   // V>>1 for this thread

        float4 a0 = make_float4(0.5f * c0.x, 0.5f * c0.y, 0.5f * c0.z, 0.5f * c0.w);
        float4 a1 = make_float4(0.5f * c1.x, 0.5f * c1.y, 0.5f * c1.z, 0.5f * c1.w);
        tap2<356, 1>(sw, hv, cm[0], a0, a1); // d=1425
        tap2<445, 0>(sw, hv, cm[1], a0, a1); // d=1780
        tap2<493, 0>(sw, hv, cm[2], a0, a1); // d=1972
        tap2<524, 1>(sw, hv, cm[3], a0, a1); // d=2097
        tap2<639, 2>(sw, hv, cm[4], a0, a1); // d=2558
        tap2<740, 1>(sw, hv, cm[5], a0, a1); // d=2961
        tap2<877, 0>(sw, hv, cm[6], a0, a1); // d=3508
        tap2<956, 1>(sw, hv, cm[7], a0, a1); // d=3825

        s_h4[s * 512 + t] = make_uint4(pk2(a0.x, a0.y), pk2(a0.z, a0.w),
                                       pk2(a1.x, a1.y), pk2(a1.z, a1.w));

        float m0 = fmaxf(fmaxf(fabsf(a0.x), fabsf(a0.y)),
                         fmaxf(fabsf(a0.z), fabsf(a0.w)));
        float m1 = fmaxf(fmaxf(fabsf(a1.x), fabsf(a1.y)),
                         fmaxf(fabsf(a1.z), fabsf(a1.w)));
        m = fmaxf(m, fmaxf(m0, m1));
        __syncthreads();          // window slot reuse guard
    }

    // ---- block max -> global atomicMax ----
#pragma unroll
    for (int off = 16; off; off >>= 1)
        m = fmaxf(m, __shfl_xor_sync(0xffffffffu, m, off));
    if (lane == 0) s_red[w] = m;
    __syncthreads();
    if (t < 32) {
        float v = (t < TPB / 32) ? s_red[t] : 0.f;
#pragma unroll
        for (int off = 8; off; off >>= 1)
            v = fmaxf(v, __shfl_xor_sync(0xffffffffu, v, off));
        if (t == 0) atomicMax(&g_maxbits, __float_as_uint(v));
    }

    // ---- device-wide epoch barrier (all NCTA co-resident) ----
    if (t == 0) {
        __threadfence();
        unsigned old = atomicAdd(&g_bar, 1u);
        unsigned target = (old - (old % NCTA)) + NCTA;
        while (*(volatile unsigned*)&g_bar < target) __nanosleep(64);
        __threadfence();
        s_inv = 1.0f / __uint_as_float(atomicMax(&g_maxbits, 0u));
    }
    __syncthreads();

    // ---- phase 2: scale fp16 stash -> out ----
    const float inv = s_inv;
#pragma unroll 1
    for (int s = 0; s < nt; s++) {
        uint4 u = s_h4[s * 512 + t];
        float2 p0 = upk2(u.x), p1 = upk2(u.y);
        float2 q0 = upk2(u.z), q1 = upk2(u.w);
        const int ob = gv0 + s * TILE_V4 + 2 * t;
        ov[ob]     = make_float4(p0.x * inv, p0.y * inv, p1.x * inv, p1.y * inv);
        ov[ob + 1] = make_float4(q0.x * inv, q0.y * inv, q1.x * inv, q1.y * inv);
    }
}

extern "C" void kernel_launch(void* const* d_in, const int* in_sizes, int n_in,
                              void* d_out, int out_size) {
    const float* x = nullptr;
    const float* gain = nullptr;
    const float* qmat = nullptr;
    for (int i = 0; i < n_in; i++) {
        if (in_sizes[i] == 8)       gain = (const float*)d_in[i];
        else if (in_sizes[i] == 64) qmat = (const float*)d_in[i];
        else                        x    = (const float*)d_in[i];
    }
    float* out = (float*)d_out;

    cudaFuncSetAttribute(fdn_fused, cudaFuncAttributeMaxDynamicSharedMemorySize,
                         SMEM_BYTES);
    fdn_fused<<<NCTA, TPB, SMEM_BYTES>>>(x, gain, qmat, out);
}

// round 14
// speedup vs baseline: 1.4533x; 1.4533x over previous
#include <cuda_runtime.h>
#include <cuda_fp16.h>
#include <cstdint>

// FDN reverb, fused persistent kernel, all-fp16 datapath:
//   y[t]   = 0.5*x[t] + sum_n c[n]*x[t-d[n]],  c[n] = 0.5*g[n]*sum_j Q[j][n]
//   out[t] = y[t] / max|y|
//
// x window: fp16, DEINTERLEAVED (even vec4s' uint2 in se[], odd in so[]),
// 4-tile circular, 1 sync/tile. Each thread owns the adjacent vec4 pair
// (V, V+1), V even -> every tap is 2-3 conflict-free LDS.64 shared by both
// outputs. Delay structure gift: R=1 taps all have even Q (4 PRMTs each);
// R=0/2 taps have odd Q (pure word selection). Accumulation in half2
// (HFMA2), two 4-tap chains to bound rounding growth. y stashed raw (the
// half2 accumulators). grid=296, 512 thr, 2 CTAs/SM, epoch barrier.

#define T_LEN    8388608
#define NCTA     296
#define TPB      512
#define TILE_V4  1024                 // vec4 per tile
#define NT7      272                  // 272 CTAs * 7 tiles + 24 * 6 = 2048
#define HMASK    2047                 // half-vec index mask (4 tiles * 512)
#define STASH_T  7
#define SMEM_BYTES (4096 * 8 + STASH_T * 512 * 16)  // 32 KB win + 56 KB stash

__device__ unsigned g_maxbits;  // monotone: deterministic across replays
__device__ unsigned g_bar;      // epoch barrier counter

__device__ __forceinline__ unsigned prmt5432(unsigned a, unsigned b) {
    unsigned r;
    asm("prmt.b32 %0, %1, %2, 0x5432;" : "=r"(r) : "r"(a), "r"(b));
    return r;
}
__device__ __forceinline__ unsigned pk2(float a, float b) {
    __half2 h = __floats2half2_rn(a, b);
    return *reinterpret_cast<unsigned*>(&h);
}
__device__ __forceinline__ float2 upk2(unsigned u) {
    __half2 h = *reinterpret_cast<__half2*>(&u);
    return __half22float2(h);
}
__device__ __forceinline__ unsigned hfma2u(unsigned c, unsigned x, unsigned a) {
    __half2 r = __hfma2(*(__half2*)&c, *(__half2*)&x, *(__half2*)&a);
    return *(unsigned*)&r;
}
__device__ __forceinline__ unsigned hmul2u(unsigned a, unsigned b) {
    __half2 r = __hmul2(*(__half2*)&a, *(__half2*)&b);
    return *(unsigned*)&r;
}
__device__ __forceinline__ unsigned hadd2u(unsigned a, unsigned b) {
    __half2 r = __hadd2(*(__half2*)&a, *(__half2*)&b);
    return *(unsigned*)&r;
}
__device__ __forceinline__ unsigned hmaxabs2u(unsigned m, unsigned v) {
    __half2 r = __hmax2(*(__half2*)&m, __habs2(*(__half2*)&v));
    return *(unsigned*)&r;
}

// Tap for output pair (V, V+1), V even, hv = V>>1, d = 4Q+R.
// a = V-Q. Parity: R==1 <=> Q even (a even); R==0/2 <=> Q odd (a odd).
template <int Q, int R>
__device__ __forceinline__ void tap2h(const uint2* __restrict__ se,
                                      const uint2* __restrict__ so,
                                      int hv, unsigned c, unsigned* acc) {
    if (R == 1) {                       // Q even: vec a = se, neighbors = so
        const int ha = (hv - Q / 2) & HMASK;
        const int hm = (ha - 1) & HMASK;
        const unsigned W1 = so[hm].y;   // hi word of vec a-1
        const uint2 Wa = se[ha];        // vec a
        const uint2 Wb = so[ha];        // vec a+1
        acc[0] = hfma2u(c, prmt5432(W1,   Wa.x), acc[0]);
        acc[1] = hfma2u(c, prmt5432(Wa.x, Wa.y), acc[1]);
        acc[2] = hfma2u(c, prmt5432(Wa.y, Wb.x), acc[2]);
        acc[3] = hfma2u(c, prmt5432(Wb.x, Wb.y), acc[3]);
    } else if (R == 0) {                // Q odd: vec a = so, a+1 = se
        const int j = (hv - (Q + 1) / 2) & HMASK;
        const uint2 Wa = so[j];                    // vec a
        const uint2 Wb = se[(j + 1) & HMASK];      // vec a+1
        acc[0] = hfma2u(c, Wa.x, acc[0]);
        acc[1] = hfma2u(c, Wa.y, acc[1]);
        acc[2] = hfma2u(c, Wb.x, acc[2]);
        acc[3] = hfma2u(c, Wb.y, acc[3]);
    } else {                            // R == 2, Q odd: word-aligned
        const int j = (hv - (Q + 1) / 2) & HMASK;
        const unsigned W1 = se[j].y;               // hi word of vec a-1
        const uint2 Wm = so[j];                    // vec a
        const unsigned W4 = se[(j + 1) & HMASK].x; // lo word of vec a+1
        acc[0] = hfma2u(c, W1,   acc[0]);
        acc[1] = hfma2u(c, Wm.x, acc[1]);
        acc[2] = hfma2u(c, Wm.y, acc[2]);
        acc[3] = hfma2u(c, W4,   acc[3]);
    }
}

__global__ void __launch_bounds__(TPB, 2)
fdn_fused(const float* __restrict__ x, const float* __restrict__ gain,
          const float* __restrict__ qmat, float* __restrict__ out) {
    extern __shared__ uint2 swin[];
    uint2* se = swin;                   // even vec4s (2048 uint2, 16 KB)
    uint2* so = swin + 2048;            // odd vec4s
    uint2* s_h2 = swin + 4096;          // fp16 y stash, uint2 view (linear in vec)
    uint4* s_h4 = (uint4*)s_h2;
    __shared__ float s_cm[8];
    __shared__ float s_red[TPB / 32];
    __shared__ float s_inv;

    const int t    = threadIdx.x;
    const int lane = t & 31;
    const int w    = t >> 5;
    const int b    = blockIdx.x;
    const int nt    = (b < NT7) ? 7 : 6;
    const int tile0 = (b < NT7) ? b * 7 : 6 * b + NT7;
    const int gv0   = tile0 * TILE_V4;
    const float4* xv = (const float4*)x;
    float4* ov = (float4*)out;

    // coefficients (fp32 in smem; per-thread half2 copies below)
    if (t < 8) {
        float s = 0.f;
#pragma unroll
        for (int j = 0; j < 8; j++) s += __ldg(qmat + j * 8 + t);
        s_cm[t] = 0.5f * s * __ldg(gain + t);
    }

    // preload halo tile (tile0-1): vecs V=2hv, V+1 -> se/so (zero below t=0)
    {
        const int g0 = gv0 - TILE_V4 + 2 * t;
        const float4 z4 = make_float4(0.f, 0.f, 0.f, 0.f);
        float4 h0 = (g0 >= 0) ? __ldg(xv + g0) : z4;
        float4 h1 = (g0 + 1 >= 0) ? __ldg(xv + g0 + 1) : z4;
        const int hv = ((tile0 - 1) * 512 + t) & HMASK;
        se[hv] = make_uint2(pk2(h0.x, h0.y), pk2(h0.z, h0.w));
        so[hv] = make_uint2(pk2(h1.x, h1.y), pk2(h1.z, h1.w));
    }
    float4 r0 = __ldg(xv + gv0 + 2 * t);
    float4 r1 = __ldg(xv + gv0 + 2 * t + 1);
    __syncthreads();

    unsigned ch[8];
#pragma unroll
    for (int n = 0; n < 8; n++) {
        __half2 h = __float2half2_rn(s_cm[n]);
        ch[n] = *reinterpret_cast<unsigned*>(&h);
    }
    const unsigned h05 = 0x38003800u;   // half2(0.5, 0.5)

    // ---- phase 1: FIR (half2); y -> stash; running |max| ----
    unsigned m2 = 0u;
#pragma unroll 1
    for (int s = 0; s < nt; s++) {
        const int hv = (tile0 + s) * 512 + t;   // this thread's V>>1
        // pack + stage tile s (slot (tile0+s)&3 holds dead tile data)
        const unsigned u0 = pk2(r0.x, r0.y), u1 = pk2(r0.z, r0.w);
        const unsigned u2 = pk2(r1.x, r1.y), u3 = pk2(r1.z, r1.w);
        se[hv & HMASK] = make_uint2(u0, u1);
        so[hv & HMASK] = make_uint2(u2, u3);
        __syncthreads();          // staging of tile s visible to all
        if (s + 1 < nt) {         // prefetch next tile under compute
            const int nb = gv0 + (s + 1) * TILE_V4 + 2 * t;
            r0 = __ldg(xv + nb);
            r1 = __ldg(xv + nb + 1);
        }

        // chain A: dry + taps 0..3 ; chain B: taps 4..7
        unsigned accA[4], accB[4];
        accA[0] = hmul2u(u0, h05); accA[1] = hmul2u(u1, h05);
        accA[2] = hmul2u(u2, h05); accA[3] = hmul2u(u3, h05);
        accB[0] = accB[1] = accB[2] = accB[3] = 0u;

        tap2h<356, 1>(se, so, hv, ch[0], accA); // d=1425
        tap2h<445, 0>(se, so, hv, ch[1], accA); // d=1780
        tap2h<493, 0>(se, so, hv, ch[2], accA); // d=1972
        tap2h<524, 1>(se, so, hv, ch[3], accA); // d=2097
        tap2h<639, 2>(se, so, hv, ch[4], accB); // d=2558
        tap2h<740, 1>(se, so, hv, ch[5], accB); // d=2961
        tap2h<877, 0>(se, so, hv, ch[6], accB); // d=3508
        tap2h<956, 1>(se, so, hv, ch[7], accB); // d=3825

        unsigned y0 = hadd2u(accA[0], accB[0]);
        unsigned y1 = hadd2u(accA[1], accB[1]);
        unsigned y2 = hadd2u(accA[2], accB[2]);
        unsigned y3 = hadd2u(accA[3], accB[3]);

        s_h4[s * 512 + t] = make_uint4(y0, y1, y2, y3);

        m2 = hmaxabs2u(m2, y0); m2 = hmaxabs2u(m2, y1);
        m2 = hmaxabs2u(m2, y2); m2 = hmaxabs2u(m2, y3);
        // no second sync: next staging targets the dead slot
    }
    __half2 mh = *reinterpret_cast<__half2*>(&m2);
    float m = fmaxf(__low2float(mh), __high2float(mh));

    // ---- block max -> global atomicMax ----
#pragma unroll
    for (int off = 16; off; off >>= 1)
        m = fmaxf(m, __shfl_xor_sync(0xffffffffu, m, off));
    if (lane == 0) s_red[w] = m;
    __syncthreads();
    if (t < 32) {
        float v = (t < TPB / 32) ? s_red[t] : 0.f;
#pragma unroll
        for (int off = 8; off; off >>= 1)
            v = fmaxf(v, __shfl_xor_sync(0xffffffffu, v, off));
        if (t == 0) atomicMax(&g_maxbits, __float_as_uint(v));
    }

    // ---- device-wide epoch barrier (all NCTA co-resident) ----
    if (t == 0) {
        __threadfence();
        unsigned old = atomicAdd(&g_bar, 1u);
        unsigned target = (old - (old % NCTA)) + NCTA;
        while (*(volatile unsigned*)&g_bar < target) __nanosleep(64);
        __threadfence();
        s_inv = 1.0f / __uint_as_float(atomicMax(&g_maxbits, 0u));
    }
    __syncthreads();

    // ---- phase 2: scale stash -> out (stash uint2 view is linear in vec) ----
    const float inv = s_inv;
#pragma unroll 1
    for (int s = 0; s < nt; s++) {
        const int base = gv0 + s * TILE_V4;
        uint2 ua = s_h2[s * 1024 + t];          // vec base + t
        uint2 ub = s_h2[s * 1024 + 512 + t];    // vec base + 512 + t
        float2 a0 = upk2(ua.x), a1 = upk2(ua.y);
        float2 b0 = upk2(ub.x), b1 = upk2(ub.y);
        ov[base + t]       = make_float4(a0.x * inv, a0.y * inv, a1.x * inv, a1.y * inv);
        ov[base + 512 + t] = make_float4(b0.x * inv, b0.y * inv, b1.x * inv, b1.y * inv);
    }
}

extern "C" void kernel_launch(void* const* d_in, const int* in_sizes, int n_in,
                              void* d_out, int out_size) {
    const float* x = nullptr;
    const float* gain = nullptr;
    const float* qmat = nullptr;
    for (int i = 0; i < n_in; i++) {
        if (in_sizes[i] == 8)       gain = (const float*)d_in[i];
        else if (in_sizes[i] == 64) qmat = (const float*)d_in[i];
        else                        x    = (const float*)d_in[i];
    }
    float* out = (float*)d_out;

    cudaFuncSetAttribute(fdn_fused, cudaFuncAttributeMaxDynamicSharedMemorySize,
                         SMEM_BYTES);
    fdn_fused<<<NCTA, TPB, SMEM_BYTES>>>(x, gain, qmat, out);
}

// round 15
// speedup vs baseline: 1.4801x; 1.0184x over previous
#include <cuda_runtime.h>
#include <cuda_fp16.h>
#include <cstdint>

// FDN reverb, fused persistent kernel, all-fp16 datapath, 3 CTAs/SM:
//   y[t]   = 0.5*x[t] + sum_n c[n]*x[t-d[n]],  c[n] = 0.5*g[n]*sum_j Q[j][n]
//   out[t] = y[t] / max|y|
//
// R13 structure (fp16 deinterleaved window, adjacent-pair outputs, half2
// FIR) with occupancy raised to 48 warps/SM: grid=444 (3 CTAs/SM on 148
// SMs, co-resident -> epoch barrier safe), SMEM 72 KB/CTA (32 KB window +
// 40 KB stash of <=5 tiles), 42-reg cap via __launch_bounds__(512,3).
// Prefetch packs to fp16 immediately after LDG (4 live regs, not 8).

#define T_LEN    8388608
#define NCTA     444
#define TPB      512
#define TILE_V4  1024                 // vec4 per tile
#define NT5      272                  // 272 CTAs * 5 tiles + 172 * 4 = 2048
#define HMASK    2047                 // half-vec index mask (4 tiles * 512)
#define STASH_T  5
#define SMEM_BYTES (4096 * 8 + STASH_T * 512 * 16)  // 32 KB + 40 KB

__device__ unsigned g_maxbits;  // monotone: deterministic across replays
__device__ unsigned g_bar;      // epoch barrier counter

__device__ __forceinline__ unsigned prmt5432(unsigned a, unsigned b) {
    unsigned r;
    asm("prmt.b32 %0, %1, %2, 0x5432;" : "=r"(r) : "r"(a), "r"(b));
    return r;
}
__device__ __forceinline__ unsigned pk2(float a, float b) {
    __half2 h = __floats2half2_rn(a, b);
    return *reinterpret_cast<unsigned*>(&h);
}
__device__ __forceinline__ float2 upk2(unsigned u) {
    __half2 h = *reinterpret_cast<__half2*>(&u);
    return __half22float2(h);
}
__device__ __forceinline__ unsigned hfma2u(unsigned c, unsigned x, unsigned a) {
    __half2 r = __hfma2(*(__half2*)&c, *(__half2*)&x, *(__half2*)&a);
    return *(unsigned*)&r;
}
__device__ __forceinline__ unsigned hmul2u(unsigned a, unsigned b) {
    __half2 r = __hmul2(*(__half2*)&a, *(__half2*)&b);
    return *(unsigned*)&r;
}
__device__ __forceinline__ unsigned hadd2u(unsigned a, unsigned b) {
    __half2 r = __hadd2(*(__half2*)&a, *(__half2*)&b);
    return *(unsigned*)&r;
}
__device__ __forceinline__ unsigned hmaxabs2u(unsigned m, unsigned v) {
    __half2 r = __hmax2(*(__half2*)&m, __habs2(*(__half2*)&v));
    return *(unsigned*)&r;
}

// Tap for output pair (V, V+1), V even, hv = V>>1, d = 4Q+R.
// a = V-Q. Parity: R==1 <=> Q even (a even); R==0/2 <=> Q odd (a odd).
template <int Q, int R>
__device__ __forceinline__ void tap2h(const uint2* __restrict__ se,
                                      const uint2* __restrict__ so,
                                      int hv, unsigned c, unsigned* acc) {
    if (R == 1) {                       // Q even: vec a = se, neighbors = so
        const int ha = (hv - Q / 2) & HMASK;
        const int hm = (ha - 1) & HMASK;
        const unsigned W1 = so[hm].y;   // hi word of vec a-1
        const uint2 Wa = se[ha];        // vec a
        const uint2 Wb = so[ha];        // vec a+1
        acc[0] = hfma2u(c, prmt5432(W1,   Wa.x), acc[0]);
        acc[1] = hfma2u(c, prmt5432(Wa.x, Wa.y), acc[1]);
        acc[2] = hfma2u(c, prmt5432(Wa.y, Wb.x), acc[2]);
        acc[3] = hfma2u(c, prmt5432(Wb.x, Wb.y), acc[3]);
    } else if (R == 0) {                // Q odd: vec a = so, a+1 = se
        const int j = (hv - (Q + 1) / 2) & HMASK;
        const uint2 Wa = so[j];                    // vec a
        const uint2 Wb = se[(j + 1) & HMASK];      // vec a+1
        acc[0] = hfma2u(c, Wa.x, acc[0]);
        acc[1] = hfma2u(c, Wa.y, acc[1]);
        acc[2] = hfma2u(c, Wb.x, acc[2]);
        acc[3] = hfma2u(c, Wb.y, acc[3]);
    } else {                            // R == 2, Q odd: word-aligned
        const int j = (hv - (Q + 1) / 2) & HMASK;
        const unsigned W1 = se[j].y;               // hi word of vec a-1
        const uint2 Wm = so[j];                    // vec a
        const unsigned W4 = se[(j + 1) & HMASK].x; // lo word of vec a+1
        acc[0] = hfma2u(c, W1,   acc[0]);
        acc[1] = hfma2u(c, Wm.x, acc[1]);
        acc[2] = hfma2u(c, Wm.y, acc[2]);
        acc[3] = hfma2u(c, W4,   acc[3]);
    }
}

__global__ void __launch_bounds__(TPB, 3)
fdn_fused(const float* __restrict__ x, const float* __restrict__ gain,
          const float* __restrict__ qmat, float* __restrict__ out) {
    extern __shared__ uint2 swin[];
    uint2* se = swin;                   // even vec4s (2048 uint2, 16 KB)
    uint2* so = swin + 2048;            // odd vec4s
    uint2* s_h2 = swin + 4096;          // fp16 y stash, uint2 view (linear)
    uint4* s_h4 = (uint4*)s_h2;
    __shared__ float s_cm[8];
    __shared__ float s_red[TPB / 32];
    __shared__ float s_inv;

    const int t    = threadIdx.x;
    const int lane = t & 31;
    const int w    = t >> 5;
    const int b    = blockIdx.x;
    const int nt    = (b < NT5) ? 5 : 4;
    const int tile0 = (b < NT5) ? b * 5 : 4 * b + NT5;
    const int gv0   = tile0 * TILE_V4;
    const float4* xv = (const float4*)x;
    float4* ov = (float4*)out;

    // coefficients
    if (t < 8) {
        float s = 0.f;
#pragma unroll
        for (int j = 0; j < 8; j++) s += __ldg(qmat + j * 8 + t);
        s_cm[t] = 0.5f * s * __ldg(gain + t);
    }

    // preload halo tile (tile0-1) -> se/so (zero below t=0)
    {
        const int g0 = gv0 - TILE_V4 + 2 * t;
        const float4 z4 = make_float4(0.f, 0.f, 0.f, 0.f);
        float4 h0 = (g0 >= 0) ? __ldg(xv + g0) : z4;
        float4 h1 = (g0 + 1 >= 0) ? __ldg(xv + g0 + 1) : z4;
        const int hv = ((tile0 - 1) * 512 + t) & HMASK;
        se[hv] = make_uint2(pk2(h0.x, h0.y), pk2(h0.z, h0.w));
        so[hv] = make_uint2(pk2(h1.x, h1.y), pk2(h1.z, h1.w));
    }
    // preload tile 0, packed immediately (only 4 live regs)
    unsigned u0, u1, u2, u3;
    {
        float4 r0 = __ldg(xv + gv0 + 2 * t);
        float4 r1 = __ldg(xv + gv0 + 2 * t + 1);
        u0 = pk2(r0.x, r0.y); u1 = pk2(r0.z, r0.w);
        u2 = pk2(r1.x, r1.y); u3 = pk2(r1.z, r1.w);
    }
    __syncthreads();

    unsigned ch[8];
#pragma unroll
    for (int n = 0; n < 8; n++) {
        __half2 h = __float2half2_rn(s_cm[n]);
        ch[n] = *reinterpret_cast<unsigned*>(&h);
    }
    const unsigned h05 = 0x38003800u;   // half2(0.5, 0.5)

    // ---- phase 1: FIR (half2); y -> stash; running |max| ----
    unsigned m2 = 0u;
#pragma unroll 1
    for (int s = 0; s < nt; s++) {
        const int hv = (tile0 + s) * 512 + t;   // this thread's V>>1
        se[hv & HMASK] = make_uint2(u0, u1);
        so[hv & HMASK] = make_uint2(u2, u3);
        __syncthreads();          // staging of tile s visible to all

        unsigned accA[4], accB[4];
        accA[0] = hmul2u(u0, h05); accA[1] = hmul2u(u1, h05);
        accA[2] = hmul2u(u2, h05); accA[3] = hmul2u(u3, h05);
        accB[0] = accB[1] = accB[2] = accB[3] = 0u;

        if (s + 1 < nt) {         // prefetch next tile; pack right away
            const int nb = gv0 + (s + 1) * TILE_V4 + 2 * t;
            float4 r0 = __ldg(xv + nb);
            float4 r1 = __ldg(xv + nb + 1);
            u0 = pk2(r0.x, r0.y); u1 = pk2(r0.z, r0.w);
            u2 = pk2(r1.x, r1.y); u3 = pk2(r1.z, r1.w);
        }

        tap2h<356, 1>(se, so, hv, ch[0], accA); // d=1425
        tap2h<445, 0>(se, so, hv, ch[1], accA); // d=1780
        tap2h<493, 0>(se, so, hv, ch[2], accA); // d=1972
        tap2h<524, 1>(se, so, hv, ch[3], accA); // d=2097
        tap2h<639, 2>(se, so, hv, ch[4], accB); // d=2558
        tap2h<740, 1>(se, so, hv, ch[5], accB); // d=2961
        tap2h<877, 0>(se, so, hv, ch[6], accB); // d=3508
        tap2h<956, 1>(se, so, hv, ch[7], accB); // d=3825

        unsigned y0 = hadd2u(accA[0], accB[0]);
        unsigned y1 = hadd2u(accA[1], accB[1]);
        unsigned y2 = hadd2u(accA[2], accB[2]);
        unsigned y3 = hadd2u(accA[3], accB[3]);

        s_h4[s * 512 + t] = make_uint4(y0, y1, y2, y3);

        m2 = hmaxabs2u(m2, y0); m2 = hmaxabs2u(m2, y1);
        m2 = hmaxabs2u(m2, y2); m2 = hmaxabs2u(m2, y3);
        // no second sync: next staging targets the dead window slot
    }
    __half2 mh = *reinterpret_cast<__half2*>(&m2);
    float m = fmaxf(__low2float(mh), __high2float(mh));

    // ---- block max -> global atomicMax ----
#pragma unroll
    for (int off = 16; off; off >>= 1)
        m = fmaxf(m, __shfl_xor_sync(0xffffffffu, m, off));
    if (lane == 0) s_red[w] = m;
    __syncthreads();
    if (t < 32) {
        float v = (t < TPB / 32) ? s_red[t] : 0.f;
#pragma unroll
        for (int off = 8; off; off >>= 1)
            v = fmaxf(v, __shfl_xor_sync(0xffffffffu, v, off));
        if (t == 0) atomicMax(&g_maxbits, __float_as_uint(v));
    }

    // ---- device-wide epoch barrier (all NCTA co-resident) ----
    if (t == 0) {
        __threadfence();
        unsigned old = atomicAdd(&g_bar, 1u);
        unsigned target = (old - (old % NCTA)) + NCTA;
        while (*(volatile unsigned*)&g_bar < target) __nanosleep(64);
        __threadfence();
        s_inv = 1.0f / __uint_as_float(atomicMax(&g_maxbits, 0u));
    }
    __syncthreads();

    // ---- phase 2: scale stash -> out ----
    const float inv = s_inv;
#pragma unroll 1
    for (int s = 0; s < nt; s++) {
        const int base = gv0 + s * TILE_V4;
        uint2 ua = s_h2[s * 1024 + t];          // vec base + t
        uint2 ub = s_h2[s * 1024 + 512 + t];    // vec base + 512 + t
        float2 a0 = upk2(ua.x), a1 = upk2(ua.y);
        float2 b0 = upk2(ub.x), b1 = upk2(ub.y);
        ov[base + t]       = make_float4(a0.x * inv, a0.y * inv, a1.x * inv, a1.y * inv);
        ov[base + 512 + t] = make_float4(b0.x * inv, b0.y * inv, b1.x * inv, b1.y * inv);
    }
}

extern "C" void kernel_launch(void* const* d_in, const int* in_sizes, int n_in,
                              void* d_out, int out_size) {
    const float* x = nullptr;
    const float* gain = nullptr;
    const float* qmat = nullptr;
    for (int i = 0; i < n_in; i++) {
        if (in_sizes[i] == 8)       gain = (const float*)d_in[i];
        else if (in_sizes[i] == 64) qmat = (const float*)d_in[i];
        else                        x    = (const float*)d_in[i];
    }
    float* out = (float*)d_out;

    cudaFuncSetAttribute(fdn_fused, cudaFuncAttributeMaxDynamicSharedMemorySize,
                         SMEM_BYTES);
    fdn_fused<<<NCTA, TPB, SMEM_BYTES>>>(x, gain, qmat, out);
}